// round 11
// baseline (speedup 1.0000x reference)
#include <cuda_runtime.h>
#include <cstdint>

#define BATCH 16
#define CIN   256
#define IMG   64
#define HW    4096
#define NHEADS 8
#define NQ    64
#define NKEY  196
#define NROWP 208
#define ATTN_SCALE 0.17677669529663687f

// Scratch (allocation-free rule: __device__ globals). All values pre-rounded tf32.
__device__ float g_q [BATCH * HW * 256];   // [b][h][w][head*32+d]
__device__ float g_kv[BATCH * HW * 512];   // [b][h][w][head*64+d]; d<32 = K, d>=32 = V
__device__ float g_xT[BATCH * HW * CIN];   // [b][m][k']  x transposed, k-permuted, tf32
__device__ float g_Wt[768 * CIN];          // [n][k']     Wq;Wkv concat, k-permuted, tf32

__device__ __forceinline__ float f2tf(float x) {
    unsigned r;
    asm("cvt.rna.tf32.f32 %0, %1;" : "=r"(r) : "f"(x));
    return __uint_as_float(r);
}
__device__ __forceinline__ unsigned fu(float x) { return __float_as_uint(x); }

__device__ __forceinline__ void mma_tf32(float& c0, float& c1, float& c2, float& c3,
                                         unsigned a0, unsigned a1, unsigned a2, unsigned a3,
                                         unsigned b0, unsigned b1) {
    asm volatile(
        "mma.sync.aligned.m16n8k8.row.col.f32.tf32.tf32.f32 "
        "{%0,%1,%2,%3},{%4,%5,%6,%7},{%8,%9},{%0,%1,%2,%3};\n"
        : "+f"(c0), "+f"(c1), "+f"(c2), "+f"(c3)
        : "r"(a0), "r"(a1), "r"(a2), "r"(a3), "r"(b0), "r"(b1));
}

// cp.async.cg 16B, L1-bypass; zero-fill when srcsz==0
__device__ __forceinline__ void cp16(unsigned dst, const void* src, int srcsz) {
    asm volatile("cp.async.cg.shared.global [%0], [%1], 16, %2;"
                 :: "r"(dst), "l"(src), "r"(srcsz));
}
__device__ __forceinline__ void cp16u(unsigned dst, const void* src) {
    asm volatile("cp.async.cg.shared.global [%0], [%1], 16;"
                 :: "r"(dst), "l"(src));
}
__device__ __forceinline__ void cp_commit() {
    asm volatile("cp.async.commit_group;");
}
__device__ __forceinline__ void cp_commit_wait_all() {
    asm volatile("cp.async.commit_group;");
    asm volatile("cp.async.wait_group 0;");
}

// component select (constant-folded under full unroll)
#define GET(v, ks) ((ks) == 0 ? (v).x : (ks) == 1 ? (v).y : (ks) == 2 ? (v).z : (v).w)

// ---------------------------------------------------------------------------
// Prep 1: g_xT[b][m][k0 + perm(kk)] = tf32(x[b][k][m]); perm(kk)=(kk%8)*4+kk/8
// 32x32 smem transpose tiles; fully coalesced both sides (perm stays in 128B).
// ---------------------------------------------------------------------------
__global__ __launch_bounds__(256) void prep_x(const float* __restrict__ x) {
    __shared__ float t[32][33];
    const int m0 = blockIdx.x << 5, k0 = blockIdx.y << 5, b = blockIdx.z;
    const int tx = threadIdx.x & 31, ty = threadIdx.x >> 5;   // 32 x 8
    const float* xb = x + (size_t)b * CIN * HW;
#pragma unroll
    for (int i = 0; i < 4; i++)
        t[ty + 8 * i][tx] = xb[(size_t)(k0 + ty + 8 * i) * HW + m0 + tx];
    __syncthreads();
    float* dst = g_xT + (size_t)b * HW * CIN;
    const int kp = k0 + (((tx & 7) << 2) | (tx >> 3));
#pragma unroll
    for (int i = 0; i < 4; i++)
        dst[(size_t)(m0 + ty + 8 * i) * CIN + kp] = f2tf(t[tx][ty + 8 * i]);
}

// Prep 2: g_Wt[n][perm(k)] = tf32(W) (Wq rows 0..255, Wkv rows 256..767)
__global__ __launch_bounds__(256) void prep_w(const float* __restrict__ Wq,
                                              const float* __restrict__ Wkv) {
    int idx = blockIdx.x * 256 + threadIdx.x;
    if (idx < 768 * CIN) {
        int n = idx >> 8, k = idx & 255;
        float v = (n < 256) ? Wq[idx] : Wkv[idx - 256 * CIN];
        int kk = k & 31;
        int kp = (k & ~31) | ((kk & 7) << 2) | (kk >> 3);
        g_Wt[n * CIN + kp] = f2tf(v);
    }
}

// ---------------------------------------------------------------------------
// Kernel 1: QKV GEMM, mma.sync tf32. 128x128 CTA tile, kTile=32, 256 threads,
// 3-stage cp.async ring. Operands pre-rounded + k-permuted -> fragment loads
// are LDS.128, zero cvt in the hot loop.
// smem stage: A[128][36] + B[128][36] floats.
// ---------------------------------------------------------------------------
#define AST2  36
#define STG2  (128 * AST2 * 2)          // 9216 floats per stage
#define GEMM_SMEM (3 * STG2 * 4)        // 110592 bytes

__global__ __launch_bounds__(256, 2) void qkv_gemm(int dummy) {
    extern __shared__ float gsm[];
    const unsigned smb = (unsigned)__cvta_generic_to_shared(gsm);

    const int nbase = blockIdx.x << 7;            // 0..640
    const int bidy  = blockIdx.y;                 // 0..511
    const int b     = bidy >> 5;
    const int mbase = (bidy & 31) << 7;

    const float* Abase = g_xT + ((size_t)b * HW + mbase) * CIN;
    const float* Bbase = g_Wt + (size_t)nbase * CIN;

    const int tid = threadIdx.x;
    const int lane = tid & 31, warp = tid >> 5;
    const int wr = warp >> 1, wc = warp & 1;
    const int g = lane >> 2, tig = lane & 3;

    const int l_r = tid >> 3, l_j = tid & 7;      // loader coords

    auto loadStage = [&](int s) {
        const unsigned base = smb + (unsigned)((s % 3) * STG2) * 4u;
        const float* as = Abase + s * 32;
        const float* bs = Bbase + s * 32;
#pragma unroll
        for (int i = 0; i < 4; i++) {
            int r = l_r + i * 32;
            cp16u(base + (unsigned)(r * AST2 + l_j * 4) * 4u, as + (size_t)r * CIN + l_j * 4);
        }
#pragma unroll
        for (int i = 0; i < 4; i++) {
            int r = l_r + i * 32;
            cp16u(base + (unsigned)((128 + r) * AST2 + l_j * 4) * 4u, bs + (size_t)r * CIN + l_j * 4);
        }
        cp_commit();
    };

    float acc[2][8][4];
#pragma unroll
    for (int mt = 0; mt < 2; mt++)
#pragma unroll
        for (int nt = 0; nt < 8; nt++)
#pragma unroll
            for (int j = 0; j < 4; j++) acc[mt][nt][j] = 0.f;

    loadStage(0); loadStage(1);

    for (int s = 0; s < 8; s++) {
        asm volatile("cp.async.wait_group 1;");
        __syncthreads();
        if (s + 2 < 8) loadStage(s + 2);
        else cp_commit();   // uniform group counting

        const float* As = gsm + (s % 3) * STG2;
        const float* Bs = As + 128 * AST2;

        // A fragments: 8 x LDS.128 cover all 4 k-steps of both m-tiles
        float4 A0[2], A1[2], A2[2], A3[2];
#pragma unroll
        for (int mt = 0; mt < 2; mt++) {
            int r = wr * 32 + mt * 16 + g;
            A0[mt] = *(const float4*)&As[r * AST2 + tig * 4];
            A1[mt] = *(const float4*)&As[(r + 8) * AST2 + tig * 4];
            A2[mt] = *(const float4*)&As[r * AST2 + (tig + 4) * 4];
            A3[mt] = *(const float4*)&As[(r + 8) * AST2 + (tig + 4) * 4];
        }
#pragma unroll
        for (int nt = 0; nt < 8; nt++) {
            int cB = wc * 64 + nt * 8 + g;
            float4 B0 = *(const float4*)&Bs[cB * AST2 + tig * 4];
            float4 B1 = *(const float4*)&Bs[cB * AST2 + (tig + 4) * 4];
#pragma unroll
            for (int ks = 0; ks < 4; ks++) {
                unsigned b0 = fu(GET(B0, ks)), b1 = fu(GET(B1, ks));
                mma_tf32(acc[0][nt][0], acc[0][nt][1], acc[0][nt][2], acc[0][nt][3],
                         fu(GET(A0[0], ks)), fu(GET(A1[0], ks)),
                         fu(GET(A2[0], ks)), fu(GET(A3[0], ks)), b0, b1);
                mma_tf32(acc[1][nt][0], acc[1][nt][1], acc[1][nt][2], acc[1][nt][3],
                         fu(GET(A0[1], ks)), fu(GET(A1[1], ks)),
                         fu(GET(A2[1], ks)), fu(GET(A3[1], ks)), b0, b1);
            }
        }
    }

    // Epilogue: pre-round to tf32, float2 stores (same as proven R8 epilogue)
    float* dst; int stride, noff;
    if (nbase < 256) { dst = g_q;  stride = 256; noff = nbase; }
    else             { dst = g_kv; stride = 512; noff = nbase - 256; }
    const size_t rowbase = (size_t)b * HW + mbase;

#pragma unroll
    for (int mt = 0; mt < 2; mt++) {
        int r = wr * 32 + mt * 16 + g;
#pragma unroll
        for (int nt = 0; nt < 8; nt++) {
            int c = wc * 64 + nt * 8 + 2 * tig;
            float2 v0 = make_float2(f2tf(acc[mt][nt][0]), f2tf(acc[mt][nt][1]));
            float2 v1 = make_float2(f2tf(acc[mt][nt][2]), f2tf(acc[mt][nt][3]));
            *(float2*)&dst[(rowbase + r    ) * stride + noff + c] = v0;
            *(float2*)&dst[(rowbase + r + 8) * stride + noff + c] = v1;
        }
    }
}

// ---------------------------------------------------------------------------
// Kernel 2: halo attention — UNCHANGED (207us, protected)
// ---------------------------------------------------------------------------
#define SMF_TOTAL 18576

__global__ __launch_bounds__(256) void halo_attn(const float* __restrict__ pb,
                                                 float* __restrict__ out) {
    extern __shared__ float smem[];
    float* Vs   = smem;
    float* Ks   = smem + 8320;
    float* Qs   = smem + 15808;
    float* Os   = smem + 15808;   // overlaps Qs (Qs dead after QK sync)
    float* redM = smem + 18112;
    float* redL = smem + 18240;
    int*  rowoff = (int*)(smem + 18368);

    const unsigned smem_b = (unsigned)__cvta_generic_to_shared(smem);
    const unsigned vs_b = smem_b;
    const unsigned ks_b = smem_b + 8320 * 4;
    const unsigned qs_b = smem_b + 15808 * 4;

    const int blk = blockIdx.x, b = blockIdx.y, head = blockIdx.z;
    const int by = blk >> 3, bx = blk & 7;

    const int tid = threadIdx.x;
    const int lane = tid & 31, warp = tid >> 5;
    const int qw = warp >> 1, kh = warp & 1;
    const int g = lane >> 2, tig = lane & 3;

    if (tid < NROWP) {
        int wy = tid / 14, wx = tid - wy * 14;
        int gh = by * 8 - 3 + wy, gw = bx * 8 - 3 + wx;
        int off = -1;
        if (tid < NKEY && (unsigned)gh < 64u && (unsigned)gw < 64u)
            off = (gh * 64 + gw) * 512;
        rowoff[tid] = off;
    }

    const float* qb = g_q + (size_t)b * HW * 256 + head * 32;
    {
        int t8 = tid & 7, r = tid >> 3;
#pragma unroll
        for (int i = 0; i < 2; i++) {
            int rr = r + i * 32;
            int gh = by * 8 + (rr >> 3), gw = bx * 8 + (rr & 7);
            cp16(qs_b + (rr * 36 + t8 * 4) * 4,
                 qb + (size_t)(gh * 64 + gw) * 256 + t8 * 4, 16);
        }
    }
    __syncthreads();

    const float* kvb = g_kv + (size_t)b * HW * 512 + head * 64;
    {
        int d4 = (tid & 15) * 4;
        int rb0 = tid >> 4;
        unsigned dstb = (d4 < 32) ? (ks_b + d4 * 4) : (vs_b + (d4 - 32) * 4);
        int dstride = (d4 < 32) ? 36 * 4 : 40 * 4;
#pragma unroll
        for (int i = 0; i < 13; i++) {
            int r = rb0 + i * 16;
            int off = rowoff[r];
            const float* src = kvb + (off >= 0 ? off : 0) + d4;
            cp16(dstb + r * dstride, src, off >= 0 ? 16 : 0);
        }
    }
    cp_commit_wait_all();
    __syncthreads();

    const int r0 = qw * 16 + g, r1 = r0 + 8;
    const int ntb = kh * 13;
    float acc[13][4];
#pragma unroll
    for (int t = 0; t < 13; t++)
#pragma unroll
        for (int j = 0; j < 4; j++) acc[t][j] = 0.f;

#pragma unroll
    for (int ks = 0; ks < 4; ks++) {
        const int k0 = ks * 8;
        unsigned a0 = fu(Qs[r0 * 36 + k0 + tig]);
        unsigned a1 = fu(Qs[r1 * 36 + k0 + tig]);
        unsigned a2 = fu(Qs[r0 * 36 + k0 + tig + 4]);
        unsigned a3 = fu(Qs[r1 * 36 + k0 + tig + 4]);
#pragma unroll
        for (int t = 0; t < 13; t++) {
            int row = (ntb + t) * 8 + g;
            unsigned b0 = fu(Ks[row * 36 + k0 + tig]);
            unsigned b1 = fu(Ks[row * 36 + k0 + tig + 4]);
            mma_tf32(acc[t][0], acc[t][1], acc[t][2], acc[t][3],
                     a0, a1, a2, a3, b0, b1);
        }
    }

    const float* pbh = pb + (size_t)head * NQ * NKEY;
    float m0 = -1e30f, m1 = -1e30f;
#pragma unroll
    for (int t = 0; t < 13; t++) {
        int c0 = (ntb + t) * 8 + 2 * tig;
        if (c0 < NKEY) {
            float2 bz0 = *(const float2*)&pbh[r0 * NKEY + c0];
            float2 bz1 = *(const float2*)&pbh[r1 * NKEY + c0];
            acc[t][0] = acc[t][0] * ATTN_SCALE + bz0.x;
            acc[t][1] = acc[t][1] * ATTN_SCALE + bz0.y;
            acc[t][2] = acc[t][2] * ATTN_SCALE + bz1.x;
            acc[t][3] = acc[t][3] * ATTN_SCALE + bz1.y;
        } else {
            acc[t][0] = acc[t][1] = acc[t][2] = acc[t][3] = -1e30f;
        }
        m0 = fmaxf(m0, fmaxf(acc[t][0], acc[t][1]));
        m1 = fmaxf(m1, fmaxf(acc[t][2], acc[t][3]));
    }
    m0 = fmaxf(m0, __shfl_xor_sync(0xffffffffu, m0, 1));
    m0 = fmaxf(m0, __shfl_xor_sync(0xffffffffu, m0, 2));
    m1 = fmaxf(m1, __shfl_xor_sync(0xffffffffu, m1, 1));
    m1 = fmaxf(m1, __shfl_xor_sync(0xffffffffu, m1, 2));

    float l0 = 0.f, l1 = 0.f;
#pragma unroll
    for (int t = 0; t < 13; t++) {
        acc[t][0] = __expf(acc[t][0] - m0);
        acc[t][1] = __expf(acc[t][1] - m0);
        acc[t][2] = __expf(acc[t][2] - m1);
        acc[t][3] = __expf(acc[t][3] - m1);
        l0 += acc[t][0] + acc[t][1];
        l1 += acc[t][2] + acc[t][3];
    }
    l0 += __shfl_xor_sync(0xffffffffu, l0, 1);
    l0 += __shfl_xor_sync(0xffffffffu, l0, 2);
    l1 += __shfl_xor_sync(0xffffffffu, l1, 1);
    l1 += __shfl_xor_sync(0xffffffffu, l1, 2);

    if (tig == 0) {
        redM[warp * 16 + g]     = m0;
        redM[warp * 16 + g + 8] = m1;
        redL[warp * 16 + g]     = l0;
        redL[warp * 16 + g + 8] = l1;
    }
    __syncthreads();
    const int ow = qw * 2 + (1 - kh);
    float mo0 = redM[ow * 16 + g], mo1 = redM[ow * 16 + g + 8];
    float lo0 = redL[ow * 16 + g], lo1 = redL[ow * 16 + g + 8];
    float M0 = fmaxf(m0, mo0), M1 = fmaxf(m1, mo1);
    float e0 = __expf(m0 - M0), e1 = __expf(m1 - M1);
    float den0 = l0 * e0 + lo0 * __expf(mo0 - M0);
    float den1 = l1 * e1 + lo1 * __expf(mo1 - M1);
    float fac0 = e0 / den0, fac1 = e1 / den1;

    float o[4][4];
#pragma unroll
    for (int nt = 0; nt < 4; nt++)
#pragma unroll
        for (int j = 0; j < 4; j++) o[nt][j] = 0.f;

    const int srcA = (lane & 28) | (tig >> 1);
    const int srcB = srcA + 2;
    const bool odd = (tig & 1);
#pragma unroll
    for (int t = 0; t < 13; t++) {
        float p00 = __shfl_sync(0xffffffffu, acc[t][0], srcA);
        float p01 = __shfl_sync(0xffffffffu, acc[t][1], srcA);
        float p10 = __shfl_sync(0xffffffffu, acc[t][2], srcA);
        float p11 = __shfl_sync(0xffffffffu, acc[t][3], srcA);
        float q00 = __shfl_sync(0xffffffffu, acc[t][0], srcB);
        float q01 = __shfl_sync(0xffffffffu, acc[t][1], srcB);
        float q10 = __shfl_sync(0xffffffffu, acc[t][2], srcB);
        float q11 = __shfl_sync(0xffffffffu, acc[t][3], srcB);
        unsigned a0 = fu(f2tf(odd ? p01 : p00));
        unsigned a1 = fu(f2tf(odd ? p11 : p10));
        unsigned a2 = fu(f2tf(odd ? q01 : q00));
        unsigned a3 = fu(f2tf(odd ? q11 : q10));
        const int krow = (ntb + t) * 8;
#pragma unroll
        for (int nt = 0; nt < 4; nt++) {
            unsigned b0 = fu(Vs[(krow + tig) * 40 + nt * 8 + g]);
            unsigned b1 = fu(Vs[(krow + tig + 4) * 40 + nt * 8 + g]);
            mma_tf32(o[nt][0], o[nt][1], o[nt][2], o[nt][3],
                     a0, a1, a2, a3, b0, b1);
        }
    }
#pragma unroll
    for (int nt = 0; nt < 4; nt++) {
        o[nt][0] *= fac0; o[nt][1] *= fac0;
        o[nt][2] *= fac1; o[nt][3] *= fac1;
    }

    if (kh == 1) {
#pragma unroll
        for (int nt = 0; nt < 4; nt++) {
            int c = nt * 8 + 2 * tig;
            *(float2*)&Os[r0 * 34 + c] = make_float2(o[nt][0], o[nt][1]);
            *(float2*)&Os[r1 * 34 + c] = make_float2(o[nt][2], o[nt][3]);
        }
    }
    __syncthreads();
    if (kh == 0) {
#pragma unroll
        for (int nt = 0; nt < 4; nt++) {
            int c = nt * 8 + 2 * tig;
            float2 u0 = *(float2*)&Os[r0 * 34 + c];
            float2 u1 = *(float2*)&Os[r1 * 34 + c];
            u0.x += o[nt][0]; u0.y += o[nt][1];
            u1.x += o[nt][2]; u1.y += o[nt][3];
            *(float2*)&Os[r0 * 34 + c] = u0;
            *(float2*)&Os[r1 * 34 + c] = u1;
        }
    }
    __syncthreads();

    const size_t ob = (size_t)b * 256 + head * 32;
    const int qx = tid & 7, d = tid >> 3;
#pragma unroll
    for (int qy = 0; qy < 8; qy++) {
        out[(ob + d) * HW + (size_t)(by * 8 + qy) * 64 + bx * 8 + qx] =
            Os[(qy * 8 + qx) * 34 + d];
    }
}

// ---------------------------------------------------------------------------
extern "C" void kernel_launch(void* const* d_in, const int* in_sizes, int n_in,
                              void* d_out, int out_size) {
    const float* x   = (const float*)d_in[0];
    const float* Wq  = (const float*)d_in[1];
    const float* Wkv = (const float*)d_in[2];
    const float* pb  = (const float*)d_in[3];
    float* out = (float*)d_out;

    cudaFuncSetAttribute(qkv_gemm, cudaFuncAttributeMaxDynamicSharedMemorySize,
                         GEMM_SMEM);
    cudaFuncSetAttribute(halo_attn, cudaFuncAttributeMaxDynamicSharedMemorySize,
                         SMF_TOTAL * (int)sizeof(float));

    prep_x<<<dim3(128, 8, 16), 256>>>(x);
    prep_w<<<768, 256>>>(Wq, Wkv);
    qkv_gemm<<<dim3(6, 512), 256, GEMM_SMEM>>>(0);
    halo_attn<<<dim3(64, 16, 8), 256, SMF_TOTAL * (int)sizeof(float)>>>(pb, out);
}